// round 11
// baseline (speedup 1.0000x reference)
#include <cuda_runtime.h>

#define B_DIM 4096
#define T_DIM 2048
#define THREADS 512
#define ITEMS 4            // T_DIM / THREADS
#define NWARP (THREADS / 32)
#define GRID 304           // 152 SMs x 2 resident blocks: persistent stride loop
#define FULL 0xffffffffu
#define RETRACE_LAMBDA 0.95f

__device__ double g_acc;            // zero at module load; reset by last block each run
__device__ unsigned int g_count;    // ditto

__global__ __launch_bounds__(THREADS, 2) void retrace_kernel(
    const float* __restrict__ cq,    // current_qf
    const float* __restrict__ tq,    // target_qf_tp1
    const float* __restrict__ tv,    // target_q_values_tp1
    const float* __restrict__ rw,    // rewards
    const float* __restrict__ pc,    // pcont
    const float* __restrict__ lp,    // logpacs
    const float* __restrict__ olp,   // old_logpacs
    const float* __restrict__ entp,  // entropy (scalar)
    const int* __restrict__ to,      // timeout (bool widened to int32)
    float* __restrict__ out)
{
    const int tid  = threadIdx.x;
    const int lane = tid & 31;
    const int warp = tid >> 5;
    const float ent = *entp;

    // double-buffered cross-warp aggregates: one barrier per iteration
    __shared__ float sA[2][NWARP], sB[2][NWARP];
    __shared__ float sErr[NWARP];
    __shared__ bool  sLast;

    float err = 0.0f;

    int r   = blockIdx.x;
    int buf = 0;
    int t0  = r * T_DIM + tid * ITEMS;       // max ~8.4M: fits int32

    // ---- prologue: issue streaming loads for first row (no reuse -> evict-first) ----
    float4 Ltq  = __ldcs((const float4*)(tq  + t0));
    float4 Ltv  = __ldcs((const float4*)(tv  + t0));
    float4 Lrw  = __ldcs((const float4*)(rw  + t0));
    float4 Lpc  = __ldcs((const float4*)(pc  + t0));
    float4 Llp  = __ldcs((const float4*)(lp  + t0));
    float4 Lolp = __ldcs((const float4*)(olp + t0));
    float4 Lcq  = __ldcs((const float4*)(cq  + t0));
    int4   Lto  = __ldcs((const int4*)(to  + t0));

    while (true) {
        // ---- consume landed loads -> per-element affine coefficients ----
        float a[ITEMS], b[ITEMS], cqv[ITEMS];
        {
            const float tqs[4]  = {Ltq.x,  Ltq.y,  Ltq.z,  Ltq.w};
            const float tvs[4]  = {Ltv.x,  Ltv.y,  Ltv.z,  Ltv.w};
            const float rws[4]  = {Lrw.x,  Lrw.y,  Lrw.z,  Lrw.w};
            const float pcs[4]  = {Lpc.x,  Lpc.y,  Lpc.z,  Lpc.w};
            const float lps[4]  = {Llp.x,  Llp.y,  Llp.z,  Llp.w};
            const float olps[4] = {Lolp.x, Lolp.y, Lolp.z, Lolp.w};
            const float cqs[4]  = {Lcq.x,  Lcq.y,  Lcq.z,  Lcq.w};
            const int   tos[4]  = {Lto.x,  Lto.y,  Lto.z,  Lto.w};

#pragma unroll
            for (int j = 0; j < ITEMS; ++j) {
                const float c  = RETRACE_LAMBDA * __expf(fminf(lps[j] - olps[j], 0.0f));
                const float mc = tos[j] ? 0.0f : c;
                b[j]   = pcs[j] * mc;
                a[j]   = rws[j] + pcs[j] * ((tvs[j] + ent) - mc * tqs[j]);
                cqv[j] = cqs[j];
            }
            // Last time step of the row: q[T-1] = tq[T-1]  (a = tq_last, b = 0)
            if (tid == THREADS - 1) {
                a[ITEMS - 1] = tqs[3];
                b[ITEMS - 1] = 0.0f;
            }
        }

        // ---- prefetch next row (raw regs now dead) ----
        const int  rn   = r + GRID;
        const bool more = (rn < B_DIM);
        if (more) {
            const int tn = rn * T_DIM + tid * ITEMS;
            Ltq  = __ldcs((const float4*)(tq  + tn));
            Ltv  = __ldcs((const float4*)(tv  + tn));
            Lrw  = __ldcs((const float4*)(rw  + tn));
            Lpc  = __ldcs((const float4*)(pc  + tn));
            Llp  = __ldcs((const float4*)(lp  + tn));
            Lolp = __ldcs((const float4*)(olp + tn));
            Lcq  = __ldcs((const float4*)(cq  + tn));
            Lto  = __ldcs((const int4*)(to  + tn));
        }

        // ---- local (per-thread) inclusive suffix scan of affine maps ----
        float A = 0.0f, Bc = 1.0f;
#pragma unroll
        for (int i = ITEMS - 1; i >= 0; --i) {
            A  = fmaf(b[i], A, a[i]);
            Bc = b[i] * Bc;
            a[i] = A;
            b[i] = Bc;
        }

        // ---- warp-level inclusive suffix scan of thread aggregates ----
#pragma unroll
        for (int off = 1; off < 32; off <<= 1) {
            const float A2 = __shfl_down_sync(FULL, A,  off);
            const float B2 = __shfl_down_sync(FULL, Bc, off);
            if (lane + off < 32) {
                A  = fmaf(Bc, A2, A);
                Bc = Bc * B2;
            }
        }

        if (lane == 0) { sA[buf][warp] = A; sB[buf][warp] = Bc; }
        __syncthreads();   // single barrier per iteration (double-buffered smem)

        // ---- every warp redundantly scans the NWARP aggregates ----
        float wA = (lane < NWARP) ? sA[buf][lane] : 0.0f;
        float wB = (lane < NWARP) ? sB[buf][lane] : 1.0f;
#pragma unroll
        for (int off = 1; off < NWARP; off <<= 1) {
            const float A2 = __shfl_down_sync(FULL, wA, off);
            const float B2 = __shfl_down_sync(FULL, wB, off);
            if (lane + off < NWARP) {
                wA = fmaf(wB, A2, wA);
                wB = wB * B2;
            }
        }
        // q entering this warp = suffix aggregate of warps > warp (lane warp+1)
        float qw = __shfl_sync(FULL, wA, warp + 1);
        if (warp == NWARP - 1) qw = 0.0f;   // exact: b[T-1] = 0

        // ---- per-thread incoming value: exclusive suffix within warp ----
        float Ae = __shfl_down_sync(FULL, A,  1);
        float Be = __shfl_down_sync(FULL, Bc, 1);
        if (lane == 31) { Ae = 0.0f; Be = 1.0f; }
        const float q_in = fmaf(Be, qw, Ae);

        // ---- materialize q and accumulate squared error (across rows) ----
#pragma unroll
        for (int i = 0; i < ITEMS; ++i) {
            const float q = fmaf(b[i], q_in, a[i]);
            const float d = cqv[i] - q;
            err = fmaf(d, d, err);
        }

        if (!more) break;
        r = rn;
        buf ^= 1;
    }

    // ---- single block reduction at the end ----
#pragma unroll
    for (int off = 16; off >= 1; off >>= 1)
        err += __shfl_down_sync(FULL, err, off);

    if (lane == 0) sErr[warp] = err;
    __syncthreads();

    if (tid == 0) {
        float s = 0.0f;
#pragma unroll
        for (int w = 0; w < NWARP; ++w) s += sErr[w];
        atomicAdd(&g_acc, (double)s);
        __threadfence();
        const unsigned int prev = atomicAdd(&g_count, 1u);
        sLast = (prev == (unsigned int)gridDim.x - 1u);
    }
    __syncthreads();

    // ---- last block finalizes and resets state for the next graph replay ----
    if (sLast && tid == 0) {
        const double acc = g_acc;   // all prior atomics visible (fence + count handshake)
        *out = (float)(acc / (double)((long long)B_DIM * (long long)T_DIM));
        g_acc = 0.0;
        __threadfence();
        g_count = 0u;               // re-arm for next replay
    }
}

extern "C" void kernel_launch(void* const* d_in, const int* in_sizes, int n_in,
                              void* d_out, int out_size) {
    const float* cq  = (const float*)d_in[0];
    const float* tq  = (const float*)d_in[1];
    const float* tv  = (const float*)d_in[2];
    const float* rw  = (const float*)d_in[3];
    const float* pc  = (const float*)d_in[4];
    const float* lp  = (const float*)d_in[5];
    const float* olp = (const float*)d_in[6];
    const float* ent = (const float*)d_in[7];
    const int*   to  = (const int*)d_in[8];
    float* out = (float*)d_out;

    retrace_kernel<<<GRID, THREADS>>>(cq, tq, tv, rw, pc, lp, olp, ent, to, out);
}

// round 12
// speedup vs baseline: 1.0028x; 1.0028x over previous
#include <cuda_runtime.h>

#define B_DIM 4096
#define T_DIM 2048
#define THREADS 512
#define ITEMS 4            // T_DIM / THREADS
#define NWARP (THREADS / 32)
#define GRID 256           // 4096 rows / 256 blocks = exactly 16 rows per block (perfect balance)
#define FULL 0xffffffffu
#define RETRACE_LAMBDA 0.95f

__device__ double g_acc;            // zero at module load; reset by last block each run
__device__ unsigned int g_count;    // ditto

__global__ __launch_bounds__(THREADS, 2) void retrace_kernel(
    const float* __restrict__ cq,    // current_qf
    const float* __restrict__ tq,    // target_qf_tp1
    const float* __restrict__ tv,    // target_q_values_tp1
    const float* __restrict__ rw,    // rewards
    const float* __restrict__ pc,    // pcont
    const float* __restrict__ lp,    // logpacs
    const float* __restrict__ olp,   // old_logpacs
    const float* __restrict__ entp,  // entropy (scalar)
    const int* __restrict__ to,      // timeout (bool widened to int32)
    float* __restrict__ out)
{
    const int tid  = threadIdx.x;
    const int lane = tid & 31;
    const int warp = tid >> 5;
    const float ent = *entp;

    // double-buffered cross-warp aggregates: one barrier per iteration
    __shared__ float sA[2][NWARP], sB[2][NWARP];
    __shared__ float sErr[NWARP];
    __shared__ bool  sLast;

    float err = 0.0f;

    int r   = blockIdx.x;
    int buf = 0;
    int t0  = r * T_DIM + tid * ITEMS;       // max ~8.4M: fits int32

    // ---- prologue: issue streaming loads for first row (no reuse -> evict-first) ----
    float4 Ltq  = __ldcs((const float4*)(tq  + t0));
    float4 Ltv  = __ldcs((const float4*)(tv  + t0));
    float4 Lrw  = __ldcs((const float4*)(rw  + t0));
    float4 Lpc  = __ldcs((const float4*)(pc  + t0));
    float4 Llp  = __ldcs((const float4*)(lp  + t0));
    float4 Lolp = __ldcs((const float4*)(olp + t0));
    float4 Lcq  = __ldcs((const float4*)(cq  + t0));
    int4   Lto  = __ldcs((const int4*)(to  + t0));

    while (true) {
        // ---- consume landed loads -> per-element affine coefficients ----
        float a[ITEMS], b[ITEMS], cqv[ITEMS];
        {
            const float tqs[4]  = {Ltq.x,  Ltq.y,  Ltq.z,  Ltq.w};
            const float tvs[4]  = {Ltv.x,  Ltv.y,  Ltv.z,  Ltv.w};
            const float rws[4]  = {Lrw.x,  Lrw.y,  Lrw.z,  Lrw.w};
            const float pcs[4]  = {Lpc.x,  Lpc.y,  Lpc.z,  Lpc.w};
            const float lps[4]  = {Llp.x,  Llp.y,  Llp.z,  Llp.w};
            const float olps[4] = {Lolp.x, Lolp.y, Lolp.z, Lolp.w};
            const float cqs[4]  = {Lcq.x,  Lcq.y,  Lcq.z,  Lcq.w};
            const int   tos[4]  = {Lto.x,  Lto.y,  Lto.z,  Lto.w};

#pragma unroll
            for (int j = 0; j < ITEMS; ++j) {
                const float c  = RETRACE_LAMBDA * __expf(fminf(lps[j] - olps[j], 0.0f));
                const float mc = tos[j] ? 0.0f : c;
                b[j]   = pcs[j] * mc;
                a[j]   = rws[j] + pcs[j] * ((tvs[j] + ent) - mc * tqs[j]);
                cqv[j] = cqs[j];
            }
            // Last time step of the row: q[T-1] = tq[T-1]  (a = tq_last, b = 0)
            if (tid == THREADS - 1) {
                a[ITEMS - 1] = tqs[3];
                b[ITEMS - 1] = 0.0f;
            }
        }

        // ---- prefetch next row (raw regs now dead) ----
        const int  rn   = r + GRID;
        const bool more = (rn < B_DIM);
        if (more) {
            const int tn = rn * T_DIM + tid * ITEMS;
            Ltq  = __ldcs((const float4*)(tq  + tn));
            Ltv  = __ldcs((const float4*)(tv  + tn));
            Lrw  = __ldcs((const float4*)(rw  + tn));
            Lpc  = __ldcs((const float4*)(pc  + tn));
            Llp  = __ldcs((const float4*)(lp  + tn));
            Lolp = __ldcs((const float4*)(olp + tn));
            Lcq  = __ldcs((const float4*)(cq  + tn));
            Lto  = __ldcs((const int4*)(to  + tn));
        }

        // ---- local (per-thread) inclusive suffix scan of affine maps ----
        float A = 0.0f, Bc = 1.0f;
#pragma unroll
        for (int i = ITEMS - 1; i >= 0; --i) {
            A  = fmaf(b[i], A, a[i]);
            Bc = b[i] * Bc;
            a[i] = A;
            b[i] = Bc;
        }

        // ---- warp-level inclusive suffix scan of thread aggregates ----
#pragma unroll
        for (int off = 1; off < 32; off <<= 1) {
            const float A2 = __shfl_down_sync(FULL, A,  off);
            const float B2 = __shfl_down_sync(FULL, Bc, off);
            if (lane + off < 32) {
                A  = fmaf(Bc, A2, A);
                Bc = Bc * B2;
            }
        }

        if (lane == 0) { sA[buf][warp] = A; sB[buf][warp] = Bc; }
        __syncthreads();   // single barrier per iteration (double-buffered smem)

        // ---- every warp redundantly scans the NWARP aggregates ----
        float wA = (lane < NWARP) ? sA[buf][lane] : 0.0f;
        float wB = (lane < NWARP) ? sB[buf][lane] : 1.0f;
#pragma unroll
        for (int off = 1; off < NWARP; off <<= 1) {
            const float A2 = __shfl_down_sync(FULL, wA, off);
            const float B2 = __shfl_down_sync(FULL, wB, off);
            if (lane + off < NWARP) {
                wA = fmaf(wB, A2, wA);
                wB = wB * B2;
            }
        }
        // q entering this warp = suffix aggregate of warps > warp (lane warp+1)
        float qw = __shfl_sync(FULL, wA, warp + 1);
        if (warp == NWARP - 1) qw = 0.0f;   // exact: b[T-1] = 0

        // ---- per-thread incoming value: exclusive suffix within warp ----
        float Ae = __shfl_down_sync(FULL, A,  1);
        float Be = __shfl_down_sync(FULL, Bc, 1);
        if (lane == 31) { Ae = 0.0f; Be = 1.0f; }
        const float q_in = fmaf(Be, qw, Ae);

        // ---- materialize q and accumulate squared error (across rows) ----
#pragma unroll
        for (int i = 0; i < ITEMS; ++i) {
            const float q = fmaf(b[i], q_in, a[i]);
            const float d = cqv[i] - q;
            err = fmaf(d, d, err);
        }

        if (!more) break;
        r = rn;
        buf ^= 1;
    }

    // ---- single block reduction at the end ----
#pragma unroll
    for (int off = 16; off >= 1; off >>= 1)
        err += __shfl_down_sync(FULL, err, off);

    if (lane == 0) sErr[warp] = err;
    __syncthreads();

    if (tid == 0) {
        float s = 0.0f;
#pragma unroll
        for (int w = 0; w < NWARP; ++w) s += sErr[w];
        atomicAdd(&g_acc, (double)s);
        __threadfence();
        const unsigned int prev = atomicAdd(&g_count, 1u);
        sLast = (prev == (unsigned int)gridDim.x - 1u);
    }
    __syncthreads();

    // ---- last block finalizes and resets state for the next graph replay ----
    if (sLast && tid == 0) {
        const double acc = g_acc;   // all prior atomics visible (fence + count handshake)
        *out = (float)(acc / (double)((long long)B_DIM * (long long)T_DIM));
        g_acc = 0.0;
        __threadfence();
        g_count = 0u;               // re-arm for next replay
    }
}

extern "C" void kernel_launch(void* const* d_in, const int* in_sizes, int n_in,
                              void* d_out, int out_size) {
    const float* cq  = (const float*)d_in[0];
    const float* tq  = (const float*)d_in[1];
    const float* tv  = (const float*)d_in[2];
    const float* rw  = (const float*)d_in[3];
    const float* pc  = (const float*)d_in[4];
    const float* lp  = (const float*)d_in[5];
    const float* olp = (const float*)d_in[6];
    const float* ent = (const float*)d_in[7];
    const int*   to  = (const int*)d_in[8];
    float* out = (float*)d_out;

    retrace_kernel<<<GRID, THREADS>>>(cq, tq, tv, rw, pc, lp, olp, ent, to, out);
}